// round 4
// baseline (speedup 1.0000x reference)
#include <cuda_runtime.h>
#include <math.h>

#define PI_D 3.14159265358979323846264338327950288

// Problem sizes: L=256, 2L-1=511, C=32, L_FREQ=128, MF=255, T_DIM=256

// ---------------- scratch (device globals; allocation-free) ----------------
__device__ float  g_P [16777216];              // [m][l][t]  256*256*256, zero for l<m
__device__ float  g_w [256];                   // quadrature weights sin(th)*dang^2
__device__ float  g_cs[256];                   // sqrt((2k+1)/(2k))
__device__ float2 g_ab[65536];                 // [m][l] recurrence coeffs (a,b)
__device__ __align__(16) float2 g_T[65536];    // [k][j] (cos,sin)(2*pi*k*j/511), k,j<256
__device__ __align__(16) float  g_xs[2097152]; // [p][t][c] folded+weighted x (sum)
__device__ __align__(16) float  g_xd[2097152]; // [p][t][c] folded+weighted x (diff)
__device__ __align__(16) float  g_Fr[2097152]; // [m][t][c]
__device__ __align__(16) float  g_Fi[2097152];
__device__ float  g_fr[2097152];               // [m][l][c] flm for m>=0
__device__ float  g_fi[2097152];
__device__ float  g_Ar[1044480];               // [lo][mo][c] resized flm
__device__ float  g_Ai[1044480];
__device__ float  g_Wr[131072];                // [l][i][o] modulated weight
__device__ float  g_Wi[131072];
__device__ float  g_Br[1044480];               // [mi][l][c] after channel mix
__device__ float  g_Bi[1044480];
__device__ __align__(16) float  g_Hc[1048576]; // [mu][t][c] m-folded cos coeff
__device__ __align__(16) float  g_Hs[1048576]; // [mu][t][c] m-folded sin coeff

// ---------------- recurrence coefficients (MUFU-heavy, tiny) ----------------
__global__ void k_coef() {
    int m = blockIdx.x, l = threadIdx.x;
    if (m == 0) {
        g_cs[l] = (l >= 1) ? sqrtf((2.f * l + 1.f) / (2.f * l)) : 0.f;
    }
    float2 ab = make_float2(0.f, 0.f);
    if (l >= m + 2) {
        float fl = (float)l, fm = (float)m;
        float denom = fl * fl - fm * fm;
        ab.x = sqrtf((4.f * fl * fl - 1.f) / denom);
        ab.y = sqrtf((2.f * fl + 1.f) * (fl - 1.f - fm) * (fl - 1.f + fm) /
                     ((2.f * fl - 3.f) * denom));
    }
    g_ab[m * 256 + l] = ab;
}

// ---------------- basis: pure-FMA recurrence using precomputed coeffs ----------------
__global__ void k_basis() {
    int m = blockIdx.x;
    int t = threadIdx.x;
    __shared__ float  cs[256];
    __shared__ float2 ab[256];
    cs[t] = g_cs[t];
    ab[t] = g_ab[m * 256 + t];
    double th = PI_D * (2.0 * t + 1.0) / 511.0;
    float ct = (float)cos(th), st = (float)sin(th);
    if (m == 0) {
        double dang = 2.0 * PI_D / 511.0;
        g_w[t] = (float)(sin(th) * dang * dang);
    }
    __syncthreads();
    float* Pm = g_P + m * 65536;
    for (int l = 0; l < m; l++) Pm[l * 256 + t] = 0.f;
    float pmm = 0.28209479177387814f;  // sqrt(1/(4*pi))
    for (int k = 1; k <= m; k++) pmm *= -cs[k] * st;
    Pm[m * 256 + t] = pmm;
    if (m + 1 < 256) {
        float pl1 = sqrtf(2.f * m + 3.f) * ct * pmm;
        Pm[(m + 1) * 256 + t] = pl1;
        float pl2 = pmm;
        for (int l = m + 2; l < 256; l++) {
            float2 c2 = ab[l];
            float p = c2.x * ct * pl1 - c2.y * pl2;
            Pm[l * 256 + t] = p;
            pl2 = pl1; pl1 = p;
        }
    }
}

// ---------------- twiddle table: (cos,sin)(2*pi*k*j/511), k,j in 0..255 ----------------
__global__ void k_ttab() {
    int k = blockIdx.x, j = threadIdx.x;
    int kj = (k * j) % 511;
    double s, c;
    sincos(2.0 * PI_D * (double)kj / 511.0, &s, &c);
    g_T[k * 256 + j] = make_float2((float)c, (float)s);
}

// ---------------- fold x over p-pairs, apply quadrature weight ----------------
__global__ void k_fold1(const float* __restrict__ x) {
    int p = blockIdx.y;
    int tid = threadIdx.x;
    int t = blockIdx.x * 8 + (tid >> 5);
    int c = tid & 31;
    float w = g_w[t];
    float a = x[((size_t)t * 511 + p) * 32 + c];
    float xs, xd;
    if (p == 0) { xs = w * a; xd = 0.f; }
    else {
        float b = x[((size_t)t * 511 + (511 - p)) * 32 + c];
        xs = w * (a + b);
        xd = w * (b - a);
    }
    size_t o = ((size_t)p * 256 + t) * 32 + c;
    g_xs[o] = xs;
    g_xd[o] = xd;
}

// ---------------- tiled dual-GEMM: Cr = cos^T * B1, Ci = sin^T * B2 ----------------
// MODE 0: B1=g_xs, B2=g_xd -> g_Fr, g_Fi (forward DFT)
// MODE 1: B1=g_Hc, B2=g_Hs -> out with p-fold epilogue
template<int KTOT, int MODE>
__global__ void __launch_bounds__(256)
k_gemm(float* __restrict__ outp) {
    const float* __restrict__ B1 = (MODE == 0) ? g_xs : g_Hc;
    const float* __restrict__ B2 = (MODE == 0) ? g_xd : g_Hs;
    __shared__ float2 As[16][64];
    __shared__ float  Bs1[16][64], Bs2[16][64];
    const int tid = threadIdx.x;
    const int m0 = blockIdx.x * 64, n0 = blockIdx.y * 64;
    const int tm = tid >> 4, tn = tid & 15;
    float cr[4][4] = {}, ci[4][4] = {};
    const int ak0 = tid >> 5,         am0 = tid & 31;
    const int ak1 = (tid + 256) >> 5, am1 = am0;
    const int bk = tid >> 4, bn = (tid & 15) << 2;

    for (int k0 = 0; k0 < KTOT; k0 += 16) {
        float4 a0  = *(const float4*)&g_T[(k0 + ak0) * 256 + m0 + am0 * 2];
        float4 a1  = *(const float4*)&g_T[(k0 + ak1) * 256 + m0 + am1 * 2];
        float4 b1v = *(const float4*)&B1[(size_t)(k0 + bk) * 8192 + n0 + bn];
        float4 b2v = *(const float4*)&B2[(size_t)(k0 + bk) * 8192 + n0 + bn];
        __syncthreads();
        *(float4*)&As[ak0][am0 * 2] = a0;
        *(float4*)&As[ak1][am1 * 2] = a1;
        *(float4*)&Bs1[bk][bn] = b1v;
        *(float4*)&Bs2[bk][bn] = b2v;
        __syncthreads();
        #pragma unroll
        for (int kk = 0; kk < 16; kk++) {
            float4 a01 = *(float4*)&As[kk][tm * 4];
            float4 a23 = *(float4*)&As[kk][tm * 4 + 2];
            float4 b1f = *(float4*)&Bs1[kk][tn * 4];
            float4 b2f = *(float4*)&Bs2[kk][tn * 4];
            float co[4] = {a01.x, a01.z, a23.x, a23.z};
            float si[4] = {a01.y, a01.w, a23.y, a23.w};
            float u1[4] = {b1f.x, b1f.y, b1f.z, b1f.w};
            float u2[4] = {b2f.x, b2f.y, b2f.z, b2f.w};
            #pragma unroll
            for (int i = 0; i < 4; i++) {
                #pragma unroll
                for (int j = 0; j < 4; j++) {
                    cr[i][j] += co[i] * u1[j];
                    ci[i][j] += si[i] * u2[j];
                }
            }
        }
    }

    if (MODE == 0) {
        #pragma unroll
        for (int i = 0; i < 4; i++) {
            int m = m0 + tm * 4 + i;
            size_t off = (size_t)m * 8192 + n0 + tn * 4;
            *(float4*)&g_Fr[off] = make_float4(cr[i][0], cr[i][1], cr[i][2], cr[i][3]);
            *(float4*)&g_Fi[off] = make_float4(ci[i][0], ci[i][1], ci[i][2], ci[i][3]);
        }
    } else {
        int n = n0 + tn * 4;
        int t = n >> 5, c = n & 31;
        #pragma unroll
        for (int i = 0; i < 4; i++) {
            int p = m0 + tm * 4 + i;
            float4 vp = make_float4(cr[i][0] + ci[i][0], cr[i][1] + ci[i][1],
                                    cr[i][2] + ci[i][2], cr[i][3] + ci[i][3]);
            *(float4*)&outp[((size_t)t * 511 + p) * 32 + c] = vp;
            if (p > 0) {
                float4 vm = make_float4(cr[i][0] - ci[i][0], cr[i][1] - ci[i][1],
                                        cr[i][2] - ci[i][2], cr[i][3] - ci[i][3]);
                *(float4*)&outp[((size_t)t * 511 + (511 - p)) * 32 + c] = vm;
            }
        }
    }
}

// ---------------- forward Legendre: flm[m][l][c] = sum_t P[m][l][t]*F[m][t][c] ----------------
__global__ void k_legfwd() {
    int lq = blockIdx.x, m = blockIdx.y;
    int c = threadIdx.x, lg = threadIdx.y;
    int tid = lg * 32 + c;
    int l0 = lq * 64;
    if (l0 + 63 < m) {
        for (int il = 0; il < 8; il++) {
            int l = l0 + lg * 8 + il;
            g_fr[(m * 256 + l) * 32 + c] = 0.f;
            g_fi[(m * 256 + l) * 32 + c] = 0.f;
        }
        return;
    }
    __shared__ float Ps[64 * 32];
    __shared__ float Frs[32 * 32];
    __shared__ float Fis[32 * 32];
    float accr[8], acci[8];
    #pragma unroll
    for (int il = 0; il < 8; il++) { accr[il] = 0.f; acci[il] = 0.f; }
    for (int tch = 0; tch < 8; tch++) {
        int tb = tch * 32;
        for (int k = 0; k < 8; k++) {
            int i = tid + k * 256;
            int ll = i >> 5, tt = i & 31;
            Ps[i] = g_P[(m * 256 + (l0 + ll)) * 256 + tb + tt];
        }
        for (int k = 0; k < 4; k++) {
            int i = tid + k * 256;
            int tl = i >> 5, cc = i & 31;
            Frs[i] = g_Fr[(m * 256 + tb + tl) * 32 + cc];
            Fis[i] = g_Fi[(m * 256 + tb + tl) * 32 + cc];
        }
        __syncthreads();
        for (int tt = 0; tt < 32; tt++) {
            float fr = Frs[tt * 32 + c], fi = Fis[tt * 32 + c];
            #pragma unroll
            for (int il = 0; il < 8; il++) {
                float p = Ps[(lg * 8 + il) * 32 + tt];
                accr[il] += p * fr;
                acci[il] += p * fi;
            }
        }
        __syncthreads();
    }
    for (int il = 0; il < 8; il++) {
        int l = l0 + lg * 8 + il;
        g_fr[(m * 256 + l) * 32 + c] = accr[il];
        g_fi[(m * 256 + l) * 32 + c] = acci[il];
    }
}

// ---------------- time embedding + weight modulation (merged) ----------------
__global__ void k_tcwmod(const float* __restrict__ t_emb,
                         const float* __restrict__ w_tr, const float* __restrict__ b_tr,
                         const float* __restrict__ w_ti, const float* __restrict__ b_ti,
                         const float* __restrict__ wr_in, const float* __restrict__ wi_in) {
    int l = blockIdx.x;           // 0..127
    int tid = threadIdx.x;        // 256
    int lane = tid & 31, wid = tid >> 5;
    __shared__ float sr[8], si[8];
    __shared__ float2 s_tc;
    float e = t_emb[tid];
    float pr = e * w_tr[tid * 128 + l];
    float pi = e * w_ti[tid * 128 + l];
    #pragma unroll
    for (int off = 16; off; off >>= 1) {
        pr += __shfl_down_sync(0xffffffffu, pr, off);
        pi += __shfl_down_sync(0xffffffffu, pi, off);
    }
    if (lane == 0) { sr[wid] = pr; si[wid] = pi; }
    __syncthreads();
    if (tid == 0) {
        float tr = b_tr[l], ti = b_ti[l];
        for (int w = 0; w < 8; w++) { tr += sr[w]; ti += si[w]; }
        s_tc = make_float2(tr, ti);
    }
    __syncthreads();
    float2 tc = s_tc;
    #pragma unroll
    for (int k = 0; k < 4; k++) {
        int io = tid + k * 256;
        float wr = wr_in[l * 1024 + io], wi = wi_in[l * 1024 + io];
        g_Wr[l * 1024 + io] = tc.x * wr - tc.y * wi;
        g_Wi[l * 1024 + io] = tc.x * wi + tc.y * wr;
    }
}

// ---------------- bilinear (antialiased) resize (256,511)->(128,255) ----------------
__global__ void k_resize() {
    int mo = blockIdx.x;   // 0..254
    int lo = blockIdx.y;   // 0..127
    int c  = threadIdx.x;  // 0..31

    float sfl = 2.f * lo + 0.5f;
    int jl0 = 2 * lo - 1;
    float wl[4]; float suml = 0.f;
    #pragma unroll
    for (int k = 0; k < 4; k++) {
        int j = jl0 + k;
        float wv = 0.f;
        if (j >= 0 && j < 256) {
            float d = fabsf(sfl - (float)j) * 0.5f;
            wv = fmaxf(0.f, 1.f - d);
        }
        wl[k] = wv; suml += wv;
    }
    #pragma unroll
    for (int k = 0; k < 4; k++) wl[k] /= suml;

    const float ks = 511.f / 255.f;
    float sfm = ((float)mo + 0.5f) * ks - 0.5f;
    int jm0 = (int)ceilf(sfm - ks);  if (jm0 < 0)   jm0 = 0;
    int jm1 = (int)floorf(sfm + ks); if (jm1 > 510) jm1 = 510;
    int nm = jm1 - jm0 + 1;
    float wm[6]; float summ = 0.f;
    for (int k = 0; k < nm; k++) {
        float d = fabsf(sfm - (float)(jm0 + k)) / ks;
        float wv = fmaxf(0.f, 1.f - d);
        wm[k] = wv; summ += wv;
    }
    for (int k = 0; k < nm; k++) wm[k] /= summ;

    float ar = 0.f, ai = 0.f;
    for (int kl = 0; kl < 4; kl++) {
        if (wl[kl] == 0.f) continue;
        int jl = jl0 + kl;
        for (int km = 0; km < nm; km++) {
            float wgt = wl[kl] * wm[km];
            int jm = jm0 + km;
            float r, i2;
            if (jm >= 255) {
                int mm = jm - 255;
                r  = g_fr[(mm * 256 + jl) * 32 + c];
                i2 = g_fi[(mm * 256 + jl) * 32 + c];
            } else {
                int mm = 255 - jm;
                float s = (mm & 1) ? -1.f : 1.f;
                r  =  s * g_fr[(mm * 256 + jl) * 32 + c];
                i2 = -s * g_fi[(mm * 256 + jl) * 32 + c];
            }
            ar += wgt * r; ai += wgt * i2;
        }
    }
    g_Ar[(lo * 255 + mo) * 32 + c] = ar;
    g_Ai[(lo * 255 + mo) * 32 + c] = ai;
}

// ---------------- per-l complex channel mix ----------------
__global__ void k_conv() {
    int l = blockIdx.x;
    int tid = threadIdx.x;           // 256
    int o = tid & 31, mg = tid >> 5;
    __shared__ float Wrs[1024], Wis[1024], Ars[256], Ais[256];
    for (int k = 0; k < 4; k++) {
        Wrs[tid + k * 256] = g_Wr[l * 1024 + tid + k * 256];
        Wis[tid + k * 256] = g_Wi[l * 1024 + tid + k * 256];
    }
    __syncthreads();
    for (int mb = 0; mb < 255; mb += 8) {
        int r = tid >> 5, cc = tid & 31;
        int mm = mb + r;
        if (mm < 255) {
            Ars[tid] = g_Ar[(l * 255 + mm) * 32 + cc];
            Ais[tid] = g_Ai[(l * 255 + mm) * 32 + cc];
        }
        __syncthreads();
        int mi = mb + mg;
        if (mi < 255) {
            float accr = 0.f, acci = 0.f;
            #pragma unroll
            for (int i = 0; i < 32; i++) {
                float ar = Ars[mg * 32 + i], ai = Ais[mg * 32 + i];
                float wr = Wrs[i * 32 + o],  wi = Wis[i * 32 + o];
                accr += ar * wr - ai * wi;
                acci += ar * wi + ai * wr;
            }
            g_Br[(mi * 128 + l) * 32 + o] = accr;
            g_Bi[(mi * 128 + l) * 32 + o] = acci;
        }
        __syncthreads();
    }
}

// ---------------- inverse Legendre fused with +/-m fold ----------------
// block (tq, mu): computes H directly:
//   Hc[mu][t][c] = Gr(+mu) + Gr(-mu),  Hs = Gi(-mu) - Gi(+mu)
// where G(m)[t][c] = sgn(m) * sum_l B[127+m][l][c] * P[|m|][l][t]
__global__ void k_leginv2() {
    int tq = blockIdx.x, mu = blockIdx.y;   // tq 0..3, mu 0..127
    int c = threadIdx.x, tg = threadIdx.y;
    int tid = tg * 32 + c;
    int mi_p = 127 + mu, mi_m = 127 - mu;
    float s = (mu & 1) ? -1.f : 1.f;
    int t0 = tq * 64;
    __shared__ float Ps[32 * 64];
    __shared__ float Bpr[32 * 32], Bpi[32 * 32], Bmr[32 * 32], Bmi[32 * 32];
    float arp[8] = {}, aip[8] = {}, arm[8] = {}, aim[8] = {};
    for (int lc = 0; lc < 4; lc++) {
        int lb = lc * 32;
        for (int k = 0; k < 8; k++) {
            int i = tid + k * 256;
            int ll = i >> 6, tt = i & 63;
            Ps[i] = g_P[(mu * 256 + lb + ll) * 256 + t0 + tt];
        }
        for (int k = 0; k < 4; k++) {
            int i = tid + k * 256;
            int ll = i >> 5, cc = i & 31;
            Bpr[i] = g_Br[(mi_p * 128 + lb + ll) * 32 + cc];
            Bpi[i] = g_Bi[(mi_p * 128 + lb + ll) * 32 + cc];
            if (mu > 0) {
                Bmr[i] = s * g_Br[(mi_m * 128 + lb + ll) * 32 + cc];
                Bmi[i] = s * g_Bi[(mi_m * 128 + lb + ll) * 32 + cc];
            } else {
                Bmr[i] = 0.f; Bmi[i] = 0.f;
            }
        }
        __syncthreads();
        for (int ll = 0; ll < 32; ll++) {
            float bpr = Bpr[ll * 32 + c], bpi = Bpi[ll * 32 + c];
            float bmr = Bmr[ll * 32 + c], bmi = Bmi[ll * 32 + c];
            #pragma unroll
            for (int k = 0; k < 8; k++) {
                float p = Ps[ll * 64 + tg * 8 + k];
                arp[k] += bpr * p;
                aip[k] += bpi * p;
                arm[k] += bmr * p;
                aim[k] += bmi * p;
            }
        }
        __syncthreads();
    }
    #pragma unroll
    for (int k = 0; k < 8; k++) {
        int t = t0 + tg * 8 + k;
        float hc = arp[k] + arm[k];
        float hs = (mu > 0) ? (aim[k] - aip[k]) : 0.f;
        g_Hc[(size_t)mu * 8192 + (size_t)t * 32 + c] = hc;
        g_Hs[(size_t)mu * 8192 + (size_t)t * 32 + c] = hs;
    }
}

// ---------------- launch ----------------
extern "C" void kernel_launch(void* const* d_in, const int* in_sizes, int n_in,
                              void* d_out, int out_size) {
    const float* x     = (const float*)d_in[0];
    const float* t_emb = (const float*)d_in[1];
    const float* wr    = (const float*)d_in[2];
    const float* wi    = (const float*)d_in[3];
    const float* w_tr  = (const float*)d_in[4];
    const float* b_tr  = (const float*)d_in[5];
    const float* w_ti  = (const float*)d_in[6];
    const float* b_ti  = (const float*)d_in[7];
    float* out = (float*)d_out;

    k_coef<<<256, 256>>>();
    k_ttab<<<256, 256>>>();
    k_basis<<<256, 256>>>();
    k_tcwmod<<<128, 256>>>(t_emb, w_tr, b_tr, w_ti, b_ti, wr, wi);
    k_fold1<<<dim3(32, 256), 256>>>(x);
    k_gemm<256, 0><<<dim3(4, 128), 256>>>(nullptr);
    k_legfwd<<<dim3(4, 256), dim3(32, 8)>>>();
    k_resize<<<dim3(255, 128), 32>>>();
    k_conv<<<128, 256>>>();
    k_leginv2<<<dim3(4, 128), dim3(32, 8)>>>();
    k_gemm<128, 1><<<dim3(4, 128), 256>>>(out);
}

// round 6
// speedup vs baseline: 1.5298x; 1.5298x over previous
#include <cuda_runtime.h>
#include <math.h>

#define PI_D 3.14159265358979323846264338327950288

// Problem sizes: L=256, 2L-1=511, C=32, L_FREQ=128, MF=255, T_DIM=256

// ---------------- scratch (device globals; allocation-free) ----------------
__device__ float  g_P [16777216];              // [m][l][t]  256*256*256, zero for l<m
__device__ float  g_w [256];                   // quadrature weights sin(th)*dang^2
__device__ float  g_cs[256];                   // sqrt((2k+1)/(2k))
__device__ float2 g_ab[65536];                 // [m][l] recurrence coeffs (a,b)
__device__ __align__(16) float2 g_T[65536];    // [k][j] (cos,sin)(2*pi*k*j/511), k,j<256
__device__ __align__(16) float  g_xs[2097152]; // [p][t][c] folded+weighted x (sum)
__device__ __align__(16) float  g_xd[2097152]; // [p][t][c] folded+weighted x (diff)
__device__ __align__(16) float  g_Fr[2097152]; // [m][t][c]
__device__ __align__(16) float  g_Fi[2097152];
__device__ float  g_fr[2097152];               // [m][l][c] flm for m>=0
__device__ float  g_fi[2097152];
__device__ float  g_Ar[1044480];               // [lo][mo][c] resized flm
__device__ float  g_Ai[1044480];
__device__ float  g_Wr[131072];                // [l][i][o] modulated weight
__device__ float  g_Wi[131072];
__device__ float  g_Br[1044480];               // [mi][l][c] after channel mix
__device__ float  g_Bi[1044480];
__device__ float  g_Gr[2088960];               // [mi][t][c]
__device__ float  g_Gi[2088960];
__device__ __align__(16) float  g_Hc[1048576]; // [mu][t][c] m-folded cos coeff
__device__ __align__(16) float  g_Hs[1048576]; // [mu][t][c] m-folded sin coeff

// ---------------- recurrence coefficients (MUFU-heavy, tiny) ----------------
__global__ void k_coef() {
    int m = blockIdx.x, l = threadIdx.x;
    if (m == 0) {
        g_cs[l] = (l >= 1) ? sqrtf((2.f * l + 1.f) / (2.f * l)) : 0.f;
    }
    float2 ab = make_float2(0.f, 0.f);
    if (l >= m + 2) {
        float fl = (float)l, fm = (float)m;
        float denom = fl * fl - fm * fm;
        ab.x = sqrtf((4.f * fl * fl - 1.f) / denom);
        ab.y = sqrtf((2.f * fl + 1.f) * (fl - 1.f - fm) * (fl - 1.f + fm) /
                     ((2.f * fl - 3.f) * denom));
    }
    g_ab[m * 256 + l] = ab;
}

// ---------------- basis: pure-FMA recurrence using precomputed coeffs ----------------
__global__ void k_basis() {
    int m = blockIdx.x;
    int t = threadIdx.x;
    __shared__ float  cs[256];
    __shared__ float2 ab[256];
    cs[t] = g_cs[t];
    ab[t] = g_ab[m * 256 + t];
    double th = PI_D * (2.0 * t + 1.0) / 511.0;
    float ct = (float)cos(th), st = (float)sin(th);
    if (m == 0) {
        double dang = 2.0 * PI_D / 511.0;
        g_w[t] = (float)(sin(th) * dang * dang);
    }
    __syncthreads();
    float* Pm = g_P + m * 65536;
    for (int l = 0; l < m; l++) Pm[l * 256 + t] = 0.f;
    float pmm = 0.28209479177387814f;  // sqrt(1/(4*pi))
    for (int k = 1; k <= m; k++) pmm *= -cs[k] * st;
    Pm[m * 256 + t] = pmm;
    if (m + 1 < 256) {
        float pl1 = sqrtf(2.f * m + 3.f) * ct * pmm;
        Pm[(m + 1) * 256 + t] = pl1;
        float pl2 = pmm;
        for (int l = m + 2; l < 256; l++) {
            float2 c2 = ab[l];
            float p = c2.x * ct * pl1 - c2.y * pl2;
            Pm[l * 256 + t] = p;
            pl2 = pl1; pl1 = p;
        }
    }
}

// ---------------- twiddle table: (cos,sin)(2*pi*k*j/511), k,j in 0..255 ----------------
__global__ void k_ttab() {
    int k = blockIdx.x, j = threadIdx.x;
    int kj = (k * j) % 511;
    double s, c;
    sincos(2.0 * PI_D * (double)kj / 511.0, &s, &c);
    g_T[k * 256 + j] = make_float2((float)c, (float)s);
}

// ---------------- fold x over p-pairs, apply quadrature weight ----------------
__global__ void k_fold1(const float* __restrict__ x) {
    int p = blockIdx.y;
    int tid = threadIdx.x;
    int t = blockIdx.x * 8 + (tid >> 5);
    int c = tid & 31;
    float w = g_w[t];
    float a = x[((size_t)t * 511 + p) * 32 + c];
    float xs, xd;
    if (p == 0) { xs = w * a; xd = 0.f; }
    else {
        float b = x[((size_t)t * 511 + (511 - p)) * 32 + c];
        xs = w * (a + b);
        xd = w * (b - a);
    }
    size_t o = ((size_t)p * 256 + t) * 32 + c;
    g_xs[o] = xs;
    g_xd[o] = xd;
}

// ---------------- tiled dual-GEMM: Cr = cos^T * B1, Ci = sin^T * B2 ----------------
// MODE 0: B1=g_xs, B2=g_xd -> g_Fr, g_Fi (forward DFT)
// MODE 1: B1=g_Hc, B2=g_Hs -> out with p-fold epilogue
template<int KTOT, int MODE>
__global__ void __launch_bounds__(256)
k_gemm(float* __restrict__ outp) {
    const float* __restrict__ B1 = (MODE == 0) ? g_xs : g_Hc;
    const float* __restrict__ B2 = (MODE == 0) ? g_xd : g_Hs;
    __shared__ float2 As[16][64];
    __shared__ float  Bs1[16][64], Bs2[16][64];
    const int tid = threadIdx.x;
    const int m0 = blockIdx.x * 64, n0 = blockIdx.y * 64;
    const int tm = tid >> 4, tn = tid & 15;
    float cr[4][4] = {}, ci[4][4] = {};
    const int ak0 = tid >> 5,         am0 = tid & 31;
    const int ak1 = (tid + 256) >> 5, am1 = am0;
    const int bk = tid >> 4, bn = (tid & 15) << 2;

    for (int k0 = 0; k0 < KTOT; k0 += 16) {
        float4 a0  = *(const float4*)&g_T[(k0 + ak0) * 256 + m0 + am0 * 2];
        float4 a1  = *(const float4*)&g_T[(k0 + ak1) * 256 + m0 + am1 * 2];
        float4 b1v = *(const float4*)&B1[(size_t)(k0 + bk) * 8192 + n0 + bn];
        float4 b2v = *(const float4*)&B2[(size_t)(k0 + bk) * 8192 + n0 + bn];
        __syncthreads();
        *(float4*)&As[ak0][am0 * 2] = a0;
        *(float4*)&As[ak1][am1 * 2] = a1;
        *(float4*)&Bs1[bk][bn] = b1v;
        *(float4*)&Bs2[bk][bn] = b2v;
        __syncthreads();
        #pragma unroll
        for (int kk = 0; kk < 16; kk++) {
            float4 a01 = *(float4*)&As[kk][tm * 4];
            float4 a23 = *(float4*)&As[kk][tm * 4 + 2];
            float4 b1f = *(float4*)&Bs1[kk][tn * 4];
            float4 b2f = *(float4*)&Bs2[kk][tn * 4];
            float co[4] = {a01.x, a01.z, a23.x, a23.z};
            float si[4] = {a01.y, a01.w, a23.y, a23.w};
            float u1[4] = {b1f.x, b1f.y, b1f.z, b1f.w};
            float u2[4] = {b2f.x, b2f.y, b2f.z, b2f.w};
            #pragma unroll
            for (int i = 0; i < 4; i++) {
                #pragma unroll
                for (int j = 0; j < 4; j++) {
                    cr[i][j] += co[i] * u1[j];
                    ci[i][j] += si[i] * u2[j];
                }
            }
        }
    }

    if (MODE == 0) {
        #pragma unroll
        for (int i = 0; i < 4; i++) {
            int m = m0 + tm * 4 + i;
            size_t off = (size_t)m * 8192 + n0 + tn * 4;
            *(float4*)&g_Fr[off] = make_float4(cr[i][0], cr[i][1], cr[i][2], cr[i][3]);
            *(float4*)&g_Fi[off] = make_float4(ci[i][0], ci[i][1], ci[i][2], ci[i][3]);
        }
    } else {
        int n = n0 + tn * 4;
        int t = n >> 5, c = n & 31;
        #pragma unroll
        for (int i = 0; i < 4; i++) {
            int p = m0 + tm * 4 + i;
            float4 vp = make_float4(cr[i][0] + ci[i][0], cr[i][1] + ci[i][1],
                                    cr[i][2] + ci[i][2], cr[i][3] + ci[i][3]);
            *(float4*)&outp[((size_t)t * 511 + p) * 32 + c] = vp;
            if (p > 0) {
                float4 vm = make_float4(cr[i][0] - ci[i][0], cr[i][1] - ci[i][1],
                                        cr[i][2] - ci[i][2], cr[i][3] - ci[i][3]);
                *(float4*)&outp[((size_t)t * 511 + (511 - p)) * 32 + c] = vm;
            }
        }
    }
}

// ---------------- forward Legendre: flm[m][l][c] = sum_t P[m][l][t]*F[m][t][c] ----------------
__global__ void k_legfwd() {
    int lq = blockIdx.x, m = blockIdx.y;
    int c = threadIdx.x, lg = threadIdx.y;
    int tid = lg * 32 + c;
    int l0 = lq * 64;
    if (l0 + 63 < m) {
        for (int il = 0; il < 8; il++) {
            int l = l0 + lg * 8 + il;
            g_fr[(m * 256 + l) * 32 + c] = 0.f;
            g_fi[(m * 256 + l) * 32 + c] = 0.f;
        }
        return;
    }
    __shared__ float Ps[64 * 32];
    __shared__ float Frs[32 * 32];
    __shared__ float Fis[32 * 32];
    float accr[8], acci[8];
    #pragma unroll
    for (int il = 0; il < 8; il++) { accr[il] = 0.f; acci[il] = 0.f; }
    for (int tch = 0; tch < 8; tch++) {
        int tb = tch * 32;
        for (int k = 0; k < 8; k++) {
            int i = tid + k * 256;
            int ll = i >> 5, tt = i & 31;
            Ps[i] = g_P[(m * 256 + (l0 + ll)) * 256 + tb + tt];
        }
        for (int k = 0; k < 4; k++) {
            int i = tid + k * 256;
            int tl = i >> 5, cc = i & 31;
            Frs[i] = g_Fr[(m * 256 + tb + tl) * 32 + cc];
            Fis[i] = g_Fi[(m * 256 + tb + tl) * 32 + cc];
        }
        __syncthreads();
        for (int tt = 0; tt < 32; tt++) {
            float fr = Frs[tt * 32 + c], fi = Fis[tt * 32 + c];
            #pragma unroll
            for (int il = 0; il < 8; il++) {
                float p = Ps[(lg * 8 + il) * 32 + tt];
                accr[il] += p * fr;
                acci[il] += p * fi;
            }
        }
        __syncthreads();
    }
    for (int il = 0; il < 8; il++) {
        int l = l0 + lg * 8 + il;
        g_fr[(m * 256 + l) * 32 + c] = accr[il];
        g_fi[(m * 256 + l) * 32 + c] = acci[il];
    }
}

// ---------------- time embedding + weight modulation (merged) ----------------
__global__ void k_tcwmod(const float* __restrict__ t_emb,
                         const float* __restrict__ w_tr, const float* __restrict__ b_tr,
                         const float* __restrict__ w_ti, const float* __restrict__ b_ti,
                         const float* __restrict__ wr_in, const float* __restrict__ wi_in) {
    int l = blockIdx.x;           // 0..127
    int tid = threadIdx.x;        // 256
    int lane = tid & 31, wid = tid >> 5;
    __shared__ float sr[8], si[8];
    __shared__ float2 s_tc;
    float e = t_emb[tid];
    float pr = e * w_tr[tid * 128 + l];
    float pi = e * w_ti[tid * 128 + l];
    #pragma unroll
    for (int off = 16; off; off >>= 1) {
        pr += __shfl_down_sync(0xffffffffu, pr, off);
        pi += __shfl_down_sync(0xffffffffu, pi, off);
    }
    if (lane == 0) { sr[wid] = pr; si[wid] = pi; }
    __syncthreads();
    if (tid == 0) {
        float tr = b_tr[l], ti = b_ti[l];
        for (int w = 0; w < 8; w++) { tr += sr[w]; ti += si[w]; }
        s_tc = make_float2(tr, ti);
    }
    __syncthreads();
    float2 tc = s_tc;
    #pragma unroll
    for (int k = 0; k < 4; k++) {
        int io = tid + k * 256;
        float wr = wr_in[l * 1024 + io], wi = wi_in[l * 1024 + io];
        g_Wr[l * 1024 + io] = tc.x * wr - tc.y * wi;
        g_Wi[l * 1024 + io] = tc.x * wi + tc.y * wr;
    }
}

// ---------------- bilinear (antialiased) resize (256,511)->(128,255) ----------------
__global__ void k_resize() {
    int mo = blockIdx.x;   // 0..254
    int lo = blockIdx.y;   // 0..127
    int c  = threadIdx.x;  // 0..31

    float sfl = 2.f * lo + 0.5f;
    int jl0 = 2 * lo - 1;
    float wl[4]; float suml = 0.f;
    #pragma unroll
    for (int k = 0; k < 4; k++) {
        int j = jl0 + k;
        float wv = 0.f;
        if (j >= 0 && j < 256) {
            float d = fabsf(sfl - (float)j) * 0.5f;
            wv = fmaxf(0.f, 1.f - d);
        }
        wl[k] = wv; suml += wv;
    }
    #pragma unroll
    for (int k = 0; k < 4; k++) wl[k] /= suml;

    const float ks = 511.f / 255.f;
    float sfm = ((float)mo + 0.5f) * ks - 0.5f;
    int jm0 = (int)ceilf(sfm - ks);  if (jm0 < 0)   jm0 = 0;
    int jm1 = (int)floorf(sfm + ks); if (jm1 > 510) jm1 = 510;
    int nm = jm1 - jm0 + 1;
    float wm[6]; float summ = 0.f;
    for (int k = 0; k < nm; k++) {
        float d = fabsf(sfm - (float)(jm0 + k)) / ks;
        float wv = fmaxf(0.f, 1.f - d);
        wm[k] = wv; summ += wv;
    }
    for (int k = 0; k < nm; k++) wm[k] /= summ;

    float ar = 0.f, ai = 0.f;
    for (int kl = 0; kl < 4; kl++) {
        if (wl[kl] == 0.f) continue;
        int jl = jl0 + kl;
        for (int km = 0; km < nm; km++) {
            float wgt = wl[kl] * wm[km];
            int jm = jm0 + km;
            float r, i2;
            if (jm >= 255) {
                int mm = jm - 255;
                r  = g_fr[(mm * 256 + jl) * 32 + c];
                i2 = g_fi[(mm * 256 + jl) * 32 + c];
            } else {
                int mm = 255 - jm;
                float s = (mm & 1) ? -1.f : 1.f;
                r  =  s * g_fr[(mm * 256 + jl) * 32 + c];
                i2 = -s * g_fi[(mm * 256 + jl) * 32 + c];
            }
            ar += wgt * r; ai += wgt * i2;
        }
    }
    g_Ar[(lo * 255 + mo) * 32 + c] = ar;
    g_Ai[(lo * 255 + mo) * 32 + c] = ai;
}

// ---------------- per-l complex channel mix ----------------
__global__ void k_conv() {
    int l = blockIdx.x;
    int tid = threadIdx.x;           // 256
    int o = tid & 31, mg = tid >> 5;
    __shared__ float Wrs[1024], Wis[1024], Ars[256], Ais[256];
    for (int k = 0; k < 4; k++) {
        Wrs[tid + k * 256] = g_Wr[l * 1024 + tid + k * 256];
        Wis[tid + k * 256] = g_Wi[l * 1024 + tid + k * 256];
    }
    __syncthreads();
    for (int mb = 0; mb < 255; mb += 8) {
        int r = tid >> 5, cc = tid & 31;
        int mm = mb + r;
        if (mm < 255) {
            Ars[tid] = g_Ar[(l * 255 + mm) * 32 + cc];
            Ais[tid] = g_Ai[(l * 255 + mm) * 32 + cc];
        }
        __syncthreads();
        int mi = mb + mg;
        if (mi < 255) {
            float accr = 0.f, acci = 0.f;
            #pragma unroll
            for (int i = 0; i < 32; i++) {
                float ar = Ars[mg * 32 + i], ai = Ais[mg * 32 + i];
                float wr = Wrs[i * 32 + o],  wi = Wis[i * 32 + o];
                accr += ar * wr - ai * wi;
                acci += ar * wi + ai * wr;
            }
            g_Br[(mi * 128 + l) * 32 + o] = accr;
            g_Bi[(mi * 128 + l) * 32 + o] = acci;
        }
        __syncthreads();
    }
}

// ---------------- inverse Legendre: G[mi][t][c] = sum_{l<128} B[mi][l][c]*sgn*P[|m|][l][t] ----------------
__global__ void k_leginv() {
    int tq = blockIdx.x, mi = blockIdx.y;
    int c = threadIdx.x, tg = threadIdx.y;
    int tid = tg * 32 + c;
    int m = mi - 127;
    int mabs = m < 0 ? -m : m;
    float s = (m < 0 && (mabs & 1)) ? -1.f : 1.f;
    int t0 = tq * 64;
    __shared__ float Ps[32 * 64], Brs[32 * 32], Bis[32 * 32];
    float accr[8], acci[8];
    #pragma unroll
    for (int k = 0; k < 8; k++) { accr[k] = 0.f; acci[k] = 0.f; }
    for (int lc = 0; lc < 4; lc++) {
        int lb = lc * 32;
        for (int k = 0; k < 8; k++) {
            int i = tid + k * 256;
            int ll = i >> 6, tt = i & 63;
            Ps[i] = g_P[(mabs * 256 + lb + ll) * 256 + t0 + tt];
        }
        for (int k = 0; k < 4; k++) {
            int i = tid + k * 256;
            int ll = i >> 5, cc = i & 31;
            Brs[i] = s * g_Br[(mi * 128 + lb + ll) * 32 + cc];
            Bis[i] = s * g_Bi[(mi * 128 + lb + ll) * 32 + cc];
        }
        __syncthreads();
        for (int ll = 0; ll < 32; ll++) {
            float br = Brs[ll * 32 + c], bi = Bis[ll * 32 + c];
            #pragma unroll
            for (int k = 0; k < 8; k++) {
                float p = Ps[ll * 64 + tg * 8 + k];
                accr[k] += br * p;
                acci[k] += bi * p;
            }
        }
        __syncthreads();
    }
    for (int k = 0; k < 8; k++) {
        int t = t0 + tg * 8 + k;
        g_Gr[((size_t)mi * 256 + t) * 32 + c] = accr[k];
        g_Gi[((size_t)mi * 256 + t) * 32 + c] = acci[k];
    }
}

// ---------------- fold G over +/-m ----------------
__global__ void k_fold2() {
    int mu = blockIdx.y;              // 0..127
    int tid = threadIdx.x;
    int t = blockIdx.x * 8 + (tid >> 5);
    int c = tid & 31;
    size_t tc = (size_t)t * 32 + c;
    float hc, hs;
    float grp = g_Gr[(size_t)(127 + mu) * 8192 + tc];
    float gip = g_Gi[(size_t)(127 + mu) * 8192 + tc];
    if (mu == 0) { hc = grp; hs = 0.f; }
    else {
        float grm = g_Gr[(size_t)(127 - mu) * 8192 + tc];
        float gim = g_Gi[(size_t)(127 - mu) * 8192 + tc];
        hc = grp + grm;
        hs = gim - gip;
    }
    g_Hc[(size_t)mu * 8192 + tc] = hc;
    g_Hs[(size_t)mu * 8192 + tc] = hs;
}

// ---------------- launch ----------------
extern "C" void kernel_launch(void* const* d_in, const int* in_sizes, int n_in,
                              void* d_out, int out_size) {
    const float* x     = (const float*)d_in[0];
    const float* t_emb = (const float*)d_in[1];
    const float* wr    = (const float*)d_in[2];
    const float* wi    = (const float*)d_in[3];
    const float* w_tr  = (const float*)d_in[4];
    const float* b_tr  = (const float*)d_in[5];
    const float* w_ti  = (const float*)d_in[6];
    const float* b_ti  = (const float*)d_in[7];
    float* out = (float*)d_out;

    k_coef<<<256, 256>>>();
    k_ttab<<<256, 256>>>();
    k_basis<<<256, 256>>>();
    k_tcwmod<<<128, 256>>>(t_emb, w_tr, b_tr, w_ti, b_ti, wr, wi);
    k_fold1<<<dim3(32, 256), 256>>>(x);
    k_gemm<256, 0><<<dim3(4, 128), 256>>>(nullptr);
    k_legfwd<<<dim3(4, 256), dim3(32, 8)>>>();
    k_resize<<<dim3(255, 128), 32>>>();
    k_conv<<<128, 256>>>();
    k_leginv<<<dim3(4, 255), dim3(32, 8)>>>();
    k_fold2<<<dim3(32, 128), 256>>>();
    k_gemm<128, 1><<<dim3(4, 128), 256>>>(out);
}